// round 13
// baseline (speedup 1.0000x reference)
#include <cuda_runtime.h>
#include <cuda_bf16.h>

// Problem constants (fixed by setup_inputs)
#define BB 8
#define T1 256
#define T2 1024
#define CC 128
#define NDIAG (T1 + T2 - 1)   // 1279

#define BIGF 10000000.0f
#define WPF  1.0f

// Phase-1 tiling
#define TJ 64
#define TI 128
#define KC2 8                 // float2 channel-pairs per chunk (16 channels)

typedef unsigned long long ull;

// Scratch (allocation-free rule: __device__ globals)
__device__ float g_cost[BB * T1 * T2];   // [b][j][i]  (each DTW thread reads its own contiguous row)
__device__ float g_loss[BB];

// ---------------------------------------------------------------------------
// Packed fp32x2 add (Blackwell; only reachable via PTX)
// ---------------------------------------------------------------------------
__device__ __forceinline__ ull f32x2_add(ull a, ull b) {
    ull r;
    asm("add.rn.f32x2 %0, %1, %2;" : "=l"(r) : "l"(a), "l"(b));
    return r;
}

// ---------------------------------------------------------------------------
// Phase 1: cost[b][j][i] = mean_c |A[b][j][c] - B[b][i][c]|
// Channel-pair packed f32x2: smem holds (A) and (-B) as float2 of adjacent
// channels. Per 2 channel-elems: add.f32x2 (diff) + 64-bit AND (abs, ALU pipe)
// + add.f32x2 (acc)  =>  1 fma-pipe instr / elem instead of 2.
// Thread's cells: j = 32h + 2*ty + {0,1} (h=0,1),  i = 32g + 2*tx + {0,1}
// (g=0..3)  -> all smem reads are consecutive 16B across the 16 tx lanes
// (conflict-free) and broadcast for A.
// ---------------------------------------------------------------------------
__global__ __launch_bounds__(256, 2) void cost_kernel(const float* __restrict__ A,
                                                      const float* __restrict__ Bf) {
    __shared__ float2 As2[KC2][TJ];    // [k2][j]   channel-pair of A
    __shared__ float2 Bs2[KC2][TI];    // [k2][i]   NEGATED channel-pair of B

    const int b  = blockIdx.z;
    const int jb = blockIdx.y * TJ;
    const int ib = blockIdx.x * TI;
    const int tid = threadIdx.x;

    const int kl2 = tid & 7;      // k2 lane for loads
    const int rowl = tid >> 3;    // row lane for loads (0..31)

    const int tx = tid & 15;
    const int ty = tid >> 4;

    const float* Ag = A + (size_t)(b * T1 + jb) * CC;
    const float* Bg = Bf + (size_t)(b * T2 + ib) * CC;

    ull acc[4][8];                 // [j-cell][i-cell], packed channel sums
#pragma unroll
    for (int u = 0; u < 4; u++)
#pragma unroll
        for (int v = 0; v < 8; v++) acc[u][v] = 0ull;

    for (int c0 = 0; c0 < CC; c0 += 2 * KC2) {
        // A tile: 64 rows x 8 k2 (2 float2/thread)
#pragma unroll
        for (int p = 0; p < 2; p++) {
            int jj = rowl + 32 * p;
            As2[kl2][jj] = *(const float2*)&Ag[jj * CC + c0 + 2 * kl2];
        }
        // B tile: 128 rows x 8 k2 (4 float2/thread), negated
#pragma unroll
        for (int p = 0; p < 4; p++) {
            int ii = rowl + 32 * p;
            float2 v = *(const float2*)&Bg[ii * CC + c0 + 2 * kl2];
            Bs2[kl2][ii] = make_float2(-v.x, -v.y);
        }
        __syncthreads();

#pragma unroll
        for (int k2 = 0; k2 < KC2; k2++) {
            ull av[4], nb[8];
#pragma unroll
            for (int h = 0; h < 2; h++) {
                ulonglong2 t = *(const ulonglong2*)&As2[k2][32 * h + 2 * ty];
                av[2 * h] = t.x; av[2 * h + 1] = t.y;
            }
#pragma unroll
            for (int g = 0; g < 4; g++) {
                ulonglong2 t = *(const ulonglong2*)&Bs2[k2][32 * g + 2 * tx];
                nb[2 * g] = t.x; nb[2 * g + 1] = t.y;
            }
#pragma unroll
            for (int u = 0; u < 4; u++)
#pragma unroll
                for (int v = 0; v < 8; v++) {
                    ull d = f32x2_add(av[u], nb[v]) & 0x7FFFFFFF7FFFFFFFull;
                    acc[u][v] = f32x2_add(acc[u][v], d);
                }
        }
        __syncthreads();
    }

    const float sc = 1.0f / (float)CC;
#pragma unroll
    for (int u = 0; u < 4; u++) {
        int jc = 32 * (u >> 1) + 2 * ty + (u & 1);
        float* dst = g_cost + (size_t)((b * T1 + jb + jc) * T2) + ib;
#pragma unroll
        for (int g = 0; g < 4; g++) {
            union { ull q; float2 f; } p0, p1;
            p0.q = acc[u][2 * g];
            p1.q = acc[u][2 * g + 1];
            float2 o = make_float2((p0.f.x + p0.f.y) * sc, (p1.f.x + p1.f.y) * sc);
            *(float2*)(dst + 32 * g + 2 * tx) = o;
        }
    }
}

// ---------------------------------------------------------------------------
// Phase 2: barrier-free register wavefront. Warps self-synchronize as a
// wavefront-of-warps: warp w's lane31 writes nv for diag d into bnd[w][d+1];
// warp w+1's lane0 spin-reads that single word. Slots are pre-filled with a
// NaN canary; a 32-bit smem store is atomic and computed values are never NaN,
// so the value itself is the sync token — no fences, no flags, no barrier.
// Per diag: 1 shfl + ~13 flops + 3 MUFU on the serial chain.
// ---------------------------------------------------------------------------
__device__ __forceinline__ float ldc_clamped(const float* __restrict__ row, int i) {
    i = min(max(i, 0), T2 - 1);
    return __ldg(row + i);
}

__global__ __launch_bounds__(T1) void dtw_kernel(const int* __restrict__ len_a,
                                                 const int* __restrict__ len_b) {
    const int b    = blockIdx.x;
    const int j    = threadIdx.x;            // 0..255
    const int warp = j >> 5;
    const int lane = j & 31;

    __shared__ float bnd[7][NDIAG + 1];      // [producer warp][slot]; slot d+1 = nv(diag d)

    // Fill with NaN canary; slot 0 = pc boundary value (BIG)
    const float CANARY = __uint_as_float(0x7FC00000u);
    for (int s = j; s < 7 * (NDIAG + 1); s += T1)
        (&bnd[0][0])[s] = CANARY;
    __syncthreads();
    if (j < 7) bnd[j][0] = BIGF;

    const float* __restrict__ crow = g_cost + (size_t)(b * T1 + j) * T2;

    const int la = len_a[b];
    const int lb = len_b[b];
    const int dtarget = la + lb - 2;         // <= 1278
    const bool wr = (j == la - 1);
    const bool prod = (lane == 31) && (warp < 7);

    float my_pc = BIGF;                      // pc[j+1] (own array slot)
    float lprev = (j == 0) ? 0.0f : BIGF;    // pcp[j]
    float resv  = 0.0f;

    __syncthreads();

    // Prime the 4-deep cost prefetch pipeline (i = d - j, clamped like reference)
    float c0 = ldc_clamped(crow, 0 - j);
    float c1 = ldc_clamped(crow, 1 - j);
    float c2 = ldc_clamped(crow, 2 - j);
    float c3 = ldc_clamped(crow, 3 - j);

    int d = 0;
    const int ngrp = (dtarget >> 2) + 1;     // groups of 4 diags, covers d=0..dtarget

    // softmin over exactly the reference's 3-value multiset:
    // {v0,v1,v2} == {max(v0,v1), min(min(v0,v1),v2), max(min(v0,v1),v2)} (exact)
#define STEP(CD) do {                                                        \
        float polled = 0.0f;                                                 \
        if (lane == 0 && warp > 0) {                                         \
            do { polled = *(volatile float*)&bnd[warp - 1][d]; }             \
            while (polled != polled);                                        \
        }                                                                    \
        float sh = __shfl_up_sync(0xffffffffu, my_pc, 1);                    \
        float lcur = (lane == 0) ? ((warp == 0) ? BIGF : polled) : sh;       \
        float v1 = my_pc + WPF;                                              \
        float mn_a = fminf(lprev, v1);                                       \
        float mx_a = fmaxf(lprev, v1);                                       \
        float v2 = lcur + WPF;                                               \
        float m   = fminf(mn_a, v2);                                         \
        float oth = fmaxf(mn_a, v2);                                         \
        float s = 1.0f + __expf((m - mx_a) * 100.0f)                         \
                       + __expf((m - oth)  * 100.0f);                        \
        float nv = (CD) + (m - 0.01f * __logf(s));                           \
        if (prod) bnd[warp][d + 1] = nv;                                     \
        if (wr && d == dtarget) resv = nv;                                   \
        lprev = lcur; my_pc = nv;                                            \
        d++;                                                                 \
    } while (0)

    for (int g = 0; g < ngrp; g++) {
        int ip = d + 4 - j;
        float n0 = ldc_clamped(crow, ip);
        float n1 = ldc_clamped(crow, ip + 1);
        float n2 = ldc_clamped(crow, ip + 2);
        float n3 = ldc_clamped(crow, ip + 3);
        STEP(c0); STEP(c1); STEP(c2); STEP(c3);
        c0 = n0; c1 = n1; c2 = n2; c3 = n3;
    }
#undef STEP

    if (wr) g_loss[b] = resv;
}

// ---------------------------------------------------------------------------
// Phase 3: deterministic fixed-order reduction of the 8 per-batch losses.
// ---------------------------------------------------------------------------
__global__ void reduce_kernel(float* __restrict__ out) {
    float s = 0.0f;
#pragma unroll
    for (int i = 0; i < BB; i++) s += g_loss[i];
    out[0] = s;
}

// ---------------------------------------------------------------------------
extern "C" void kernel_launch(void* const* d_in, const int* in_sizes, int n_in,
                              void* d_out, int out_size) {
    (void)in_sizes; (void)n_in; (void)out_size;
    const float* fa = (const float*)d_in[0];   // fea_a  [8,256,128] f32
    const int*   la = (const int*)  d_in[1];   // len_a  [8] i32
    const float* fb = (const float*)d_in[2];   // fea_b  [8,1024,128] f32
    const int*   lb = (const int*)  d_in[3];   // len_b  [8] i32

    dim3 g1(T2 / TI, T1 / TJ, BB);             // (8,4,8) = 256 blocks
    cost_kernel<<<g1, 256>>>(fa, fb);
    dtw_kernel<<<BB, T1>>>(la, lb);
    reduce_kernel<<<1, 1>>>((float*)d_out);
}

// round 14
// speedup vs baseline: 3.0055x; 3.0055x over previous
#include <cuda_runtime.h>
#include <cuda_bf16.h>

// Problem constants (fixed by setup_inputs)
#define BB 8
#define T1 256
#define T2 1024
#define CC 128
#define NDIAG (T1 + T2 - 1)   // 1279

#define BIGF 10000000.0f
#define WPF  1.0f

// Phase-1 tiling (R12 version — measured 27.5us, near fma-pipe roofline)
#define TJ 64
#define TI 128
#define KC 16

// Phase-2 halo wavefront
#define NW 10                 // warps per DTW block
#define DTW_THREADS (NW * 32) // 320
#define HALO 4                // redundant columns per warp / diags per barrier
#define OWN 28                // owned columns per warp

// Scratch (allocation-free rule: __device__ globals)
__device__ float g_cost[BB * T1 * T2];   // [b][j][i]
__device__ float g_loss[BB];

// ---------------------------------------------------------------------------
// Phase 1: cost[b][j][i] = mean_c |A[b][j][c] - B[b][i][c]|
// GEMM-style smem tiling, 4x8 register blocking, conflict-free split-float4
// B reads (R12 version, verbatim).
// ---------------------------------------------------------------------------
__global__ __launch_bounds__(256) void cost_kernel(const float* __restrict__ A,
                                                   const float* __restrict__ Bf) {
    __shared__ float As[KC][TJ + 4];   // [k][j]
    __shared__ float Bs[KC][TI + 4];   // [k][i]

    const int b  = blockIdx.z;
    const int jb = blockIdx.y * TJ;
    const int ib = blockIdx.x * TI;
    const int tid = threadIdx.x;

    const int kl = tid & 15;
    const int rl = tid >> 4;

    const int tx = tid & 15;
    const int ty = tid >> 4;
    const int j0 = ty * 4;
    const int ia = tx * 4;
    const int ib2 = 64 + tx * 4;

    const float* Ag = A + (size_t)(b * T1 + jb) * CC;
    const float* Bg = Bf + (size_t)(b * T2 + ib) * CC;

    float acc[4][8];
#pragma unroll
    for (int u = 0; u < 4; u++)
#pragma unroll
        for (int v = 0; v < 8; v++) acc[u][v] = 0.0f;

    for (int c0 = 0; c0 < CC; c0 += KC) {
#pragma unroll
        for (int p = 0; p < 4; p++) {
            int jj = rl + p * 16;
            As[kl][jj] = Ag[jj * CC + c0 + kl];
        }
#pragma unroll
        for (int p = 0; p < 8; p++) {
            int ii = rl + p * 16;
            Bs[kl][ii] = Bg[ii * CC + c0 + kl];
        }
        __syncthreads();

#pragma unroll
        for (int kk = 0; kk < KC; kk++) {
            float4 a4 = *(const float4*)&As[kk][j0];
            float4 b0 = *(const float4*)&Bs[kk][ia];
            float4 b1 = *(const float4*)&Bs[kk][ib2];
            float av[4] = {a4.x, a4.y, a4.z, a4.w};
            float bv[8] = {b0.x, b0.y, b0.z, b0.w, b1.x, b1.y, b1.z, b1.w};
#pragma unroll
            for (int u = 0; u < 4; u++)
#pragma unroll
                for (int v = 0; v < 8; v++)
                    acc[u][v] += fabsf(av[u] - bv[v]);
        }
        __syncthreads();
    }

    const float sc = 1.0f / (float)CC;
#pragma unroll
    for (int u = 0; u < 4; u++) {
        float* dst = g_cost + (size_t)((b * T1 + jb + j0 + u) * T2) + ib;
        float4 o0 = make_float4(acc[u][0] * sc, acc[u][1] * sc, acc[u][2] * sc, acc[u][3] * sc);
        float4 o1 = make_float4(acc[u][4] * sc, acc[u][5] * sc, acc[u][6] * sc, acc[u][7] * sc);
        *(float4*)(dst + ia)  = o0;
        *(float4*)(dst + ib2) = o1;
    }
}

// ---------------------------------------------------------------------------
// Phase 2: halo wavefront.
//   col = 28*warp - 4 + lane.  Lanes 0-3: halo (redundant), lanes 4-31: owned.
//   State per thread: cur  = value of (diag d-1, col)      [pc]
//                     lprev= value of (diag d-2, col-1)    [pcp, via old shfl]
//   Within a 4-diag superstep lane l is correct through relative diag l, so
//   owned lanes (l>=4) are always exact. One __syncthreads per 4 diags:
//   lanes 28-31 publish (cur,lprev); lanes 0-3 of the next warp refresh.
//   Virtual column -1 is pinned to BIG by masking col<0 lanes' updates.
// ---------------------------------------------------------------------------
__device__ __forceinline__ float ldc_clamped(const float* __restrict__ row, int i) {
    i = min(max(i, 0), T2 - 1);
    return __ldg(row + i);
}

__global__ __launch_bounds__(DTW_THREADS) void dtw_kernel(const int* __restrict__ len_a,
                                                          const int* __restrict__ len_b) {
    const int b    = blockIdx.x;
    const int tid  = threadIdx.x;
    const int warp = tid >> 5;
    const int lane = tid & 31;
    const int col  = OWN * warp - HALO + lane;     // -4 .. 315

    __shared__ float2 pub[2][NW][HALO];            // [parity][producer warp][lane]

    const int colc = min(max(col, 0), T1 - 1);     // clamped for memory only
    const float* __restrict__ crow = g_cost + (size_t)(b * T1 + colc) * T2;

    const int la = len_a[b];
    const int lb = len_b[b];
    const int dtarget = la + lb - 2;               // <= 1278
    const bool wr    = (lane >= HALO) && (col == la - 1);  // unique owned writer
    const bool valid = (col >= 0);                 // col<0 pinned to BIG

    float cur   = BIGF;                            // pc0: all BIG
    float lprev = (col == 0) ? 0.0f : BIGF;        // pcp0: 0 at position 0
    float resv  = 0.0f;

    // Prime 4-deep cost prefetch (i = d - col, clamped exactly like reference)
    float c0 = ldc_clamped(crow, 0 - col);
    float c1 = ldc_clamped(crow, 1 - col);
    float c2 = ldc_clamped(crow, 2 - col);
    float c3 = ldc_clamped(crow, 3 - col);

    int d = 0;
    const int nss = (dtarget >> 2) + 1;            // supersteps of 4 diags

    // softmin over exactly the reference's 3-value multiset:
    // {v0,v1,v2} == {max(v0,v1), min(min(v0,v1),v2), max(min(v0,v1),v2)} (exact)
#define STEP(CD) do {                                                        \
        float lcur = __shfl_up_sync(0xffffffffu, cur, 1);  /* lane0: halo */ \
        float v1 = cur + WPF;                                                \
        float mn_a = fminf(lprev, v1);                                       \
        float mx_a = fmaxf(lprev, v1);                                       \
        float v2 = lcur + WPF;                                               \
        float m   = fminf(mn_a, v2);                                         \
        float oth = fmaxf(mn_a, v2);                                         \
        float s = 1.0f + __expf((m - mx_a) * 100.0f)                         \
                       + __expf((m - oth)  * 100.0f);                        \
        float nv = (CD) + (m - 0.01f * __logf(s));                           \
        nv = valid ? nv : BIGF;                                              \
        if (wr && d == dtarget) resv = nv;                                   \
        lprev = lcur; cur = nv;                                              \
        d++;                                                                 \
    } while (0)

    for (int ss = 0; ss < nss; ss++) {
        int ip = d + 4 - col;
        float n0 = ldc_clamped(crow, ip);
        float n1 = ldc_clamped(crow, ip + 1);
        float n2 = ldc_clamped(crow, ip + 2);
        float n3 = ldc_clamped(crow, ip + 3);

        STEP(c0); STEP(c1); STEP(c2); STEP(c3);
        c0 = n0; c1 = n1; c2 = n2; c3 = n3;

        // Boundary exchange: one barrier per 4 diagonals, parity-buffered.
        if (lane >= 32 - HALO && warp < NW - 1)
            pub[ss & 1][warp][lane - (32 - HALO)] = make_float2(cur, lprev);
        __syncthreads();
        if (lane < HALO && warp > 0) {
            float2 t = pub[ss & 1][warp - 1][lane];
            cur = t.x; lprev = t.y;
        }
    }
#undef STEP

    if (wr) g_loss[b] = resv;
}

// ---------------------------------------------------------------------------
// Phase 3: deterministic fixed-order reduction of the 8 per-batch losses.
// ---------------------------------------------------------------------------
__global__ void reduce_kernel(float* __restrict__ out) {
    float s = 0.0f;
#pragma unroll
    for (int i = 0; i < BB; i++) s += g_loss[i];
    out[0] = s;
}

// ---------------------------------------------------------------------------
extern "C" void kernel_launch(void* const* d_in, const int* in_sizes, int n_in,
                              void* d_out, int out_size) {
    (void)in_sizes; (void)n_in; (void)out_size;
    const float* fa = (const float*)d_in[0];   // fea_a  [8,256,128] f32
    const int*   la = (const int*)  d_in[1];   // len_a  [8] i32
    const float* fb = (const float*)d_in[2];   // fea_b  [8,1024,128] f32
    const int*   lb = (const int*)  d_in[3];   // len_b  [8] i32

    dim3 g1(T2 / TI, T1 / TJ, BB);             // (8,4,8) = 256 blocks
    cost_kernel<<<g1, 256>>>(fa, fb);
    dtw_kernel<<<BB, DTW_THREADS>>>(la, lb);
    reduce_kernel<<<1, 1>>>((float*)d_out);
}